// round 8
// baseline (speedup 1.0000x reference)
#include <cuda_runtime.h>
#include <math.h>

// ---------------- problem constants ----------------
#define BB      16
#define TENC    256
#define TDEC    200
#define NMELS   80
#define EDIM    512
#define PRE     256
#define HID     1024     // ARNN == DRNN
#define ATT     128
#define NFILT   32
#define KSZ     31
#define NG      4096     // 4*HID

#define MEL_OFF   0
#define GATE_OFF  (BB*NMELS*TDEC)          /* 256000 */
#define ALIGN_OFF (GATE_OFF + BB*TDEC)     /* 259200 */

#define NBLK    148
#define NTHR    256
#define GWARPS  (NBLK*8)                   /* 1184 */

// JAX threefry scheme: 1 = partitionable (default in modern JAX), 0 = original
#define THREEFRY_PARTITIONABLE 1

typedef unsigned long long ull;

// ---------------- device scratch (no allocs allowed) ----------------
__device__ float g_x1 [TDEC*BB*PRE];
__device__ float g_pre[TDEC*BB*PRE];
__device__ float g_pm [BB*TENC*ATT];
__device__ float g_partial[32*BB*NG];          // [chunk][b][4096]
__device__ float g_ah[BB*HID];
__device__ float g_ac[BB*HID];
__device__ float g_dh[BB*HID];
__device__ float g_dc[BB*HID];
__device__ float g_ctx[BB*EDIM];
__device__ float g_aw [BB*TENC];
__device__ float g_awc[BB*TENC];
__device__ float g_pq [BB*ATT];
__device__ float g_e  [BB*TENC];

__device__ unsigned g_bar_count;
__device__ volatile unsigned g_bar_epoch;

// ---------------- threefry-2x32-20 ----------------
__host__ __device__ __forceinline__ void tf2x32(unsigned ks0, unsigned ks1,
                                                unsigned x0, unsigned x1,
                                                unsigned &o0, unsigned &o1)
{
    unsigned ks2 = ks0 ^ ks1 ^ 0x1BD11BDAu;
    x0 += ks0; x1 += ks1;
#define TFR(r) { x0 += x1; x1 = (x1 << (r)) | (x1 >> (32 - (r))); x1 ^= x0; }
    TFR(13) TFR(15) TFR(26) TFR(6)
    x0 += ks1; x1 += ks2 + 1u;
    TFR(17) TFR(29) TFR(16) TFR(24)
    x0 += ks2; x1 += ks0 + 2u;
    TFR(13) TFR(15) TFR(26) TFR(6)
    x0 += ks0; x1 += ks1 + 3u;
    TFR(17) TFR(29) TFR(16) TFR(24)
    x0 += ks1; x1 += ks2 + 4u;
    TFR(13) TFR(15) TFR(26) TFR(6)
    x0 += ks2; x1 += ks0 + 5u;
#undef TFR
    o0 = x0; o1 = x1;
}

__device__ __forceinline__ bool mask_keep(unsigned ka, unsigned kb, unsigned idx)
{
#if THREEFRY_PARTITIONABLE
    unsigned a, b;
    tf2x32(ka, kb, 0u, idx, a, b);
    return ((a ^ b) & 0x80000000u) == 0u;
#else
    const unsigned half = 411648u;   // 201*16*256 / 2
    unsigned a, b;
    if (idx < half) { tf2x32(ka, kb, idx, half + idx, a, b); return (a & 0x80000000u) == 0u; }
    else            { tf2x32(ka, kb, idx - half, idx, a, b); return (b & 0x80000000u) == 0u; }
#endif
}

__device__ __forceinline__ float sigf(float x) { return 1.0f / (1.0f + expf(-x)); }

__device__ __forceinline__ void fma2(ull &acc, ull x, ull w) {
    asm("fma.rn.f32x2 %0, %1, %2, %0;" : "+l"(acc) : "l"(x), "l"(w));
}

// ---------------- precompute kernels ----------------
__global__ __launch_bounds__(256) void k_prenet1(const float* __restrict__ dec,
                                                 const float* __restrict__ W1,
                                                 unsigned ka, unsigned kb)
{
    int idx = blockIdx.x * 256 + threadIdx.x;           // < 819200
    int t = idx >> 12;
    int r = idx & 4095;
    int b = r >> 8;
    int j = r & 255;
    float s = 0.f;
    if (t > 0) {
        const float* di = dec + b * (NMELS * TDEC) + (t - 1);
#pragma unroll 8
        for (int m = 0; m < NMELS; ++m)
            s += di[m * TDEC] * W1[m * PRE + j];
    }
    s = fmaxf(s, 0.f);
    s = mask_keep(ka, kb, (unsigned)idx) ? s * 2.0f : 0.f;
    g_x1[idx] = s;
}

__global__ __launch_bounds__(256) void k_prenet2(const float* __restrict__ W2,
                                                 unsigned ka, unsigned kb)
{
    int idx = blockIdx.x * 256 + threadIdx.x;
    int j = idx & 255;
    const float* x = g_x1 + (idx - j);
    float s0 = 0.f, s1 = 0.f;
#pragma unroll 8
    for (int m = 0; m < PRE; m += 2) {
        s0 += x[m]     * W2[m * PRE + j];
        s1 += x[m + 1] * W2[(m + 1) * PRE + j];
    }
    float s = fmaxf(s0 + s1, 0.f);
    s = mask_keep(ka, kb, (unsigned)idx) ? s * 2.0f : 0.f;
    g_pre[idx] = s;
}

__global__ __launch_bounds__(256) void k_pm(const float* __restrict__ memory,
                                            const float* __restrict__ Wmem)
{
    int idx = blockIdx.x * 256 + threadIdx.x;           // < 524288
    int a = idx & 127;
    int bt = idx >> 7;
    const float* me = memory + bt * EDIM;
    float s0 = 0.f, s1 = 0.f;
#pragma unroll 8
    for (int e = 0; e < EDIM; e += 2) {
        s0 += me[e]     * Wmem[e * ATT + a];
        s1 += me[e + 1] * Wmem[(e + 1) * ATT + a];
    }
    g_pm[idx] = s0 + s1;
}

__global__ __launch_bounds__(256) void k_init()
{
    int idx = blockIdx.x * 256 + threadIdx.x;
    if (idx == 0) { g_bar_count = 0u; g_bar_epoch = 0u; }
    if (idx < BB * HID) { g_ah[idx] = 0.f; g_ac[idx] = 0.f; g_dh[idx] = 0.f; g_dc[idx] = 0.f; }
    if (idx < BB * EDIM) g_ctx[idx] = 0.f;
    if (idx < BB * TENC) { g_aw[idx] = 0.f; g_awc[idx] = 0.f; }
}

// ---------------- grid barrier (all 148 blocks co-resident) ----------------
__device__ __forceinline__ void gbar(unsigned &epoch)
{
    epoch += 1u;
    __syncthreads();
    if (threadIdx.x == 0) {
        __threadfence();
        if (atomicAdd(&g_bar_count, 1u) == NBLK - 1u) {
            g_bar_count = 0u;
            __threadfence();
            g_bar_epoch = epoch;
        } else {
            while (g_bar_epoch < epoch) { __nanosleep(64); }
        }
    }
    __syncthreads();
}

// ---------------- persistent-kernel phase helpers ----------------
__shared__ __align__(16) float2 s_x2[80 * 16];
__shared__ float s_rb[TENC];
__shared__ float s_sw[TENC];

// GEMM partials: blocks 0..127, (chunk = bid&31, jg = bid>>5)
template<int L0, int L1, int CH, int MODE>
__device__ void gemm_phase(const float* __restrict__ Wih,
                           const float* __restrict__ Whh, int st)
{
    constexpr int IN = L0 + L1;
    int bid = blockIdx.x, tid = threadIdx.x;
    int chunk = bid & 31;
    int jg    = bid >> 5;
    int i0    = chunk * CH;

    for (int s = tid; s < CH * 16; s += NTHR) {
        int il = s >> 4, b = s & 15;
        int i = i0 + il;
        float v;
        if (i < L0)
            v = (MODE == 0) ? g_pre[st * (BB * PRE) + b * PRE + i]
                            : __ldcg(&g_ah[b * HID + i]);
        else if (i < IN)
            v = __ldcg(&g_ctx[b * EDIM + (i - L0)]);
        else
            v = (MODE == 0) ? __ldcg(&g_ah[b * HID + (i - IN)])
                            : __ldcg(&g_dh[b * HID + (i - IN)]);
        s_x2[il * 16 + b] = make_float2(v, v);
    }
    __syncthreads();

    int j0 = jg * 1024 + tid * 4;
    ull accA[16], accB[16];
#pragma unroll
    for (int b = 0; b < 16; ++b) { accA[b] = 0ull; accB[b] = 0ull; }

#pragma unroll 2
    for (int il = 0; il < CH; ++il) {
        int i = i0 + il;
        const float* wr = (i < IN) ? (Wih + (size_t)i * NG)
                                   : (Whh + (size_t)(i - IN) * NG);
        ulonglong2 w = *reinterpret_cast<const ulonglong2*>(wr + j0);
        const ulonglong2* xq = reinterpret_cast<const ulonglong2*>(s_x2 + il * 16);
#pragma unroll
        for (int bp = 0; bp < 8; ++bp) {
            ulonglong2 x2 = xq[bp];
            fma2(accA[2 * bp],     x2.x, w.x); fma2(accB[2 * bp],     x2.x, w.y);
            fma2(accA[2 * bp + 1], x2.y, w.x); fma2(accB[2 * bp + 1], x2.y, w.y);
        }
    }

    float* pout = g_partial + (size_t)chunk * (BB * NG) + j0;
#pragma unroll
    for (int b = 0; b < 16; ++b) {
        ulonglong2 v; v.x = accA[b]; v.y = accB[b];
        *reinterpret_cast<ulonglong2*>(pout + (size_t)b * NG) = v;
    }
}

// reduce 32 partials + bias + LSTM cell (blocks 0..63)
template<int MODE>
__device__ void cell_phase(const float* __restrict__ bias)
{
    int gid = blockIdx.x * NTHR + threadIdx.x;
    if (gid >= BB * HID) return;
    int b = gid >> 10, u = gid & 1023;

    float z[4];
#pragma unroll
    for (int g = 0; g < 4; ++g) {
        float s = bias[g * HID + u];
        const float* pp = g_partial + (size_t)b * NG + g * HID + u;
#pragma unroll
        for (int c = 0; c < 32; ++c) s += __ldcg(pp + (size_t)c * (BB * NG));
        z[g] = s;
    }
    float* cstate = (MODE == 0) ? g_ac : g_dc;
    float* hstate = (MODE == 0) ? g_ah : g_dh;
    float cn = sigf(z[1]) * cstate[gid] + sigf(z[0]) * tanhf(z[2]);
    float hn = sigf(z[3]) * tanhf(cn);
    cstate[gid] = cn;
    hstate[gid] = hn;
}

// pq = ah @ Wq : warp per output
__device__ void pq_phase(const float* __restrict__ Wq, int wg, int lane)
{
    for (int o = wg; o < BB * ATT; o += GWARPS) {
        int b = o >> 7, a = o & 127;
        const float* h = g_ah + b * HID;
        float s = 0.f;
#pragma unroll 8
        for (int k = lane; k < HID; k += 32)
            s += __ldcg(h + k) * Wq[(size_t)k * ATT + a];
#pragma unroll
        for (int off = 16; off > 0; off >>= 1) s += __shfl_down_sync(0xffffffffu, s, off);
        if (lane == 0) g_pq[o] = s;
    }
}

// conv + location dense + energy : warp per (b, t_enc)
__device__ void energy_phase(const float* __restrict__ lconv,
                             const float* __restrict__ ldense,
                             const float* __restrict__ vw,
                             const int* __restrict__ lens, int wg, int lane)
{
    for (int task = wg; task < BB * TENC; task += GWARPS) {
        int b = task >> 8;
        int t = task & 255;

        const float* w0 = lconv + lane * (2 * KSZ);
        const float* w1 = w0 + KSZ;
        const float* awb  = g_aw  + b * TENC;
        const float* awcb = g_awc + b * TENC;
        float lr = 0.f;
#pragma unroll
        for (int k = 0; k < KSZ; ++k) {
            int tp = t + k - 15;
            if (tp >= 0 && tp < TENC)
                lr += __ldcg(awb + tp) * w0[k] + __ldcg(awcb + tp) * w1[k];
        }

        float s0 = 0.f, s1 = 0.f, s2 = 0.f, s3 = 0.f;
#pragma unroll
        for (int f = 0; f < NFILT; ++f) {
            float lrf = __shfl_sync(0xffffffffu, lr, f);
            const float* wd = ldense + f * ATT + lane;
            s0 += lrf * wd[0];
            s1 += lrf * wd[32];
            s2 += lrf * wd[64];
            s3 += lrf * wd[96];
        }
        const float* pqb = g_pq + b * ATT + lane;
        const float* pmb = g_pm + (size_t)(b * TENC + t) * ATT + lane;
        const float* vwl = vw + lane;
        float ep = tanhf(__ldcg(pqb)      + s0 + pmb[0])  * vwl[0]
                 + tanhf(__ldcg(pqb + 32) + s1 + pmb[32]) * vwl[32]
                 + tanhf(__ldcg(pqb + 64) + s2 + pmb[64]) * vwl[64]
                 + tanhf(__ldcg(pqb + 96) + s3 + pmb[96]) * vwl[96];
#pragma unroll
        for (int off = 16; off > 0; off >>= 1) ep += __shfl_down_sync(0xffffffffu, ep, off);
        if (lane == 0)
            g_e[b * TENC + t] = (t >= lens[b]) ? -1.0e9f : ep;
    }
}

// softmax + aw/awc + alignment + context : block b (bid < 16)
__device__ void softctx_phase(const float* __restrict__ memory, float* __restrict__ out, int st)
{
    int b = blockIdx.x, tid = threadIdx.x;
    float v = __ldcg(&g_e[b * TENC + tid]);
    s_rb[tid] = v; __syncthreads();
#pragma unroll
    for (int o = 128; o > 0; o >>= 1) { if (tid < o) s_rb[tid] = fmaxf(s_rb[tid], s_rb[tid + o]); __syncthreads(); }
    float mx = s_rb[0]; __syncthreads();
    float p = expf(v - mx);
    s_rb[tid] = p; __syncthreads();
#pragma unroll
    for (int o = 128; o > 0; o >>= 1) { if (tid < o) s_rb[tid] += s_rb[tid + o]; __syncthreads(); }
    float w = p / s_rb[0];

    g_aw[b * TENC + tid] = w;
    g_awc[b * TENC + tid] += w;   // own block's prior write: same SM, coherent
    out[ALIGN_OFF + (size_t)b * (TDEC * TENC) + st * TENC + tid] = w;
    s_sw[tid] = w; __syncthreads();

    const float* mb = memory + (size_t)b * (TENC * EDIM);
    float c0 = 0.f, c1 = 0.f;
#pragma unroll 16
    for (int s = 0; s < TENC; ++s) {
        float ws = s_sw[s];
        c0 += ws * mb[(size_t)s * EDIM + tid];
        c1 += ws * mb[(size_t)s * EDIM + 256 + tid];
    }
    g_ctx[b * EDIM + tid] = c0;
    g_ctx[b * EDIM + 256 + tid] = c1;
}

// projection + gate for step st : warp-task pool [w0, w0+nw)
__device__ void proj_phase(const float* __restrict__ pW, const float* __restrict__ pb,
                           const float* __restrict__ gW, const float* __restrict__ gb,
                           float* __restrict__ out, int st, int w0, int nw, int lane)
{
    for (int o = w0; o < BB * NMELS + BB; o += nw) {
        float s = 0.f;
        if (o < BB * NMELS) {
            int b = o / NMELS, m = o % NMELS;
            const float* hd = g_dh + b * HID;
            const float* cx = g_ctx + b * EDIM;
#pragma unroll 8
            for (int k = lane; k < HID; k += 32)
                s += __ldcg(hd + k) * pW[(size_t)k * NMELS + m];
#pragma unroll 8
            for (int k = lane; k < EDIM; k += 32)
                s += __ldcg(cx + k) * pW[(size_t)(HID + k) * NMELS + m];
#pragma unroll
            for (int off = 16; off > 0; off >>= 1) s += __shfl_down_sync(0xffffffffu, s, off);
            if (lane == 0)
                out[MEL_OFF + (size_t)b * (NMELS * TDEC) + m * TDEC + st] = s + pb[m];
        } else {
            int b = o - BB * NMELS;
            const float* hd = g_dh + b * HID;
            const float* cx = g_ctx + b * EDIM;
#pragma unroll 8
            for (int k = lane; k < HID; k += 32) s += __ldcg(hd + k) * gW[k];
#pragma unroll 8
            for (int k = lane; k < EDIM; k += 32) s += __ldcg(cx + k) * gW[HID + k];
#pragma unroll
            for (int off = 16; off > 0; off >>= 1) s += __shfl_down_sync(0xffffffffu, s, off);
            if (lane == 0)
                out[GATE_OFF + b * TDEC + st] = s + gb[0];
        }
    }
}

// ---------------- the persistent decoder kernel ----------------
__global__ __launch_bounds__(NTHR) void k_decoder(
    const float* __restrict__ memory,
    const int*   __restrict__ lens,
    const float* __restrict__ aWih, const float* __restrict__ aWhh, const float* __restrict__ ab,
    const float* __restrict__ Wq,   const float* __restrict__ vw,
    const float* __restrict__ lconv, const float* __restrict__ ldense,
    const float* __restrict__ dWih, const float* __restrict__ dWhh, const float* __restrict__ db,
    const float* __restrict__ projW, const float* __restrict__ projb,
    const float* __restrict__ gateW, const float* __restrict__ gateb,
    float* __restrict__ out)
{
    int bid = blockIdx.x, tid = threadIdx.x;
    int wg = bid * 8 + (tid >> 5);
    int lane = tid & 31;
    unsigned epoch = 0u;

    for (int st = 0; st < TDEC; ++st) {
        // P1: attention-LSTM GEMM (blocks 0..127) || projection of step st-1 (blocks 128..147)
        if (bid < 128) {
            gemm_phase<PRE, EDIM, (PRE + EDIM + HID) / 32, 0>(aWih, aWhh, st);
        } else if (st > 0) {
            int wloc = (bid - 128) * 8 + (tid >> 5);
            proj_phase(projW, projb, gateW, gateb, out, st - 1, wloc, 160, lane);
        }
        gbar(epoch);

        // P2: attention LSTM cell
        cell_phase<0>(ab);
        gbar(epoch);

        // P3: pq
        pq_phase(Wq, wg, lane);
        gbar(epoch);

        // P4: conv + dense + energy
        energy_phase(lconv, ldense, vw, lens, wg, lane);
        gbar(epoch);

        // P5: softmax + context (blocks 0..15)
        if (bid < BB) softctx_phase(memory, out, st);
        gbar(epoch);

        // P6: decoder-LSTM GEMM
        if (bid < 128) {
            gemm_phase<HID, EDIM, (HID + EDIM + HID) / 32, 1>(dWih, dWhh, st);
        }
        gbar(epoch);

        // P7: decoder LSTM cell
        cell_phase<1>(db);
        gbar(epoch);
    }

    // final projection for step TDEC-1 (all warps)
    proj_phase(projW, projb, gateW, gateb, out, TDEC - 1, wg, GWARPS, lane);
}

// ---------------- launcher ----------------
extern "C" void kernel_launch(void* const* d_in, const int* in_sizes, int n_in,
                              void* d_out, int out_size)
{
    (void)in_sizes; (void)n_in; (void)out_size;
    const float* memory = (const float*)d_in[0];
    const float* dec    = (const float*)d_in[1];
    const int*   lens   = (const int*)  d_in[2];
    const float* pW1    = (const float*)d_in[3];
    const float* pW2    = (const float*)d_in[4];
    const float* aWih   = (const float*)d_in[5];
    const float* aWhh   = (const float*)d_in[6];
    const float* ab     = (const float*)d_in[7];
    const float* Wq     = (const float*)d_in[8];
    const float* Wmem   = (const float*)d_in[9];
    const float* vw     = (const float*)d_in[10];
    const float* lconv  = (const float*)d_in[11];
    const float* ldense = (const float*)d_in[12];
    const float* dWih   = (const float*)d_in[13];
    const float* dWhh   = (const float*)d_in[14];
    const float* db     = (const float*)d_in[15];
    const float* projW  = (const float*)d_in[16];
    const float* projb  = (const float*)d_in[17];
    const float* gateW  = (const float*)d_in[18];
    const float* gateb  = (const float*)d_in[19];
    float* out = (float*)d_out;

    // dropout keys: key(42) = (0,42); split -> k1, k2
    unsigned k1a, k1b, k2a, k2b;
#if THREEFRY_PARTITIONABLE
    tf2x32(0u, 42u, 0u, 0u, k1a, k1b);
    tf2x32(0u, 42u, 0u, 1u, k2a, k2b);
#else
    {
        unsigned a0, b0, a1, b1;
        tf2x32(0u, 42u, 0u, 2u, a0, b0);
        tf2x32(0u, 42u, 1u, 3u, a1, b1);
        k1a = a0; k1b = a1; k2a = b0; k2b = b1;
    }
#endif

    k_prenet1<<<3200, 256>>>(dec, pW1, k1a, k1b);
    k_prenet2<<<3200, 256>>>(pW2, k2a, k2b);
    k_pm<<<2048, 256>>>(memory, Wmem);
    k_init<<<64, 256>>>();

    k_decoder<<<NBLK, NTHR>>>(memory, lens,
                              aWih, aWhh, ab, Wq, vw, lconv, ldense,
                              dWih, dWhh, db, projW, projb, gateW, gateb, out);
}

// round 9
// speedup vs baseline: 1.1080x; 1.1080x over previous
#include <cuda_runtime.h>
#include <math.h>

// ---------------- problem constants ----------------
#define BB      16
#define TENC    256
#define TDEC    200
#define NMELS   80
#define EDIM    512
#define PRE     256
#define HID     1024     // ARNN == DRNN
#define ATT     128
#define NFILT   32
#define KSZ     31
#define NG      4096     // 4*HID

#define MEL_OFF   0
#define GATE_OFF  (BB*NMELS*TDEC)          /* 256000 */
#define ALIGN_OFF (GATE_OFF + BB*TDEC)     /* 259200 */

#define NBLK    148
#define NTHR    512
#define GWARPS  (NBLK*16)                  /* 2368 */

#define THREEFRY_PARTITIONABLE 1

typedef unsigned long long ull;

// ---------------- device scratch (no allocs allowed) ----------------
__device__ float  g_x1 [TDEC*BB*PRE];
__device__ float  g_pre[TDEC*BB*PRE];
__device__ float  g_pm [BB*TENC*ATT];
__device__ float  g_partial[32*BB*NG];         // [chunk][b][4096]
__device__ float  g_ah[BB*HID];
__device__ float  g_ac[BB*HID];
__device__ float  g_dh[BB*HID];
__device__ float  g_dc[BB*HID];
__device__ float  g_ctx[BB*EDIM];
__device__ float2 g_awpair[BB*TENC];           // (aw, awc)
__device__ float  g_pq [BB*ATT];
__device__ float  g_e  [BB*TENC];
__device__ float  g_loc[BB*TENC*ATT];          // location features (2 MB)
__device__ float2 g_lconv2[NFILT*KSZ];         // packed (W[f][0][k], W[f][1][k])
__device__ float2 g_ldense2[NFILT*64];         // packed col pairs

__device__ unsigned g_bar_count;
__device__ volatile unsigned g_bar_epoch;

// ---------------- threefry-2x32-20 ----------------
__host__ __device__ __forceinline__ void tf2x32(unsigned ks0, unsigned ks1,
                                                unsigned x0, unsigned x1,
                                                unsigned &o0, unsigned &o1)
{
    unsigned ks2 = ks0 ^ ks1 ^ 0x1BD11BDAu;
    x0 += ks0; x1 += ks1;
#define TFR(r) { x0 += x1; x1 = (x1 << (r)) | (x1 >> (32 - (r))); x1 ^= x0; }
    TFR(13) TFR(15) TFR(26) TFR(6)
    x0 += ks1; x1 += ks2 + 1u;
    TFR(17) TFR(29) TFR(16) TFR(24)
    x0 += ks2; x1 += ks0 + 2u;
    TFR(13) TFR(15) TFR(26) TFR(6)
    x0 += ks0; x1 += ks1 + 3u;
    TFR(17) TFR(29) TFR(16) TFR(24)
    x0 += ks1; x1 += ks2 + 4u;
    TFR(13) TFR(15) TFR(26) TFR(6)
    x0 += ks2; x1 += ks0 + 5u;
#undef TFR
    o0 = x0; o1 = x1;
}

__device__ __forceinline__ bool mask_keep(unsigned ka, unsigned kb, unsigned idx)
{
#if THREEFRY_PARTITIONABLE
    unsigned a, b;
    tf2x32(ka, kb, 0u, idx, a, b);
    return ((a ^ b) & 0x80000000u) == 0u;
#else
    const unsigned half = 411648u;
    unsigned a, b;
    if (idx < half) { tf2x32(ka, kb, idx, half + idx, a, b); return (a & 0x80000000u) == 0u; }
    else            { tf2x32(ka, kb, idx - half, idx, a, b); return (b & 0x80000000u) == 0u; }
#endif
}

// ---------------- fast transcendentals ----------------
__device__ __forceinline__ float ftanh(float x) {
    x = fminf(fmaxf(x, -15.f), 15.f);
    float e = __expf(2.f * x);
    return __fdividef(e - 1.f, e + 1.f);
}
__device__ __forceinline__ float fsig(float x) {
    x = fminf(fmaxf(x, -40.f), 40.f);
    return __fdividef(1.f, 1.f + __expf(-x));
}

__device__ __forceinline__ void fma2(ull &acc, ull x, ull w) {
    asm("fma.rn.f32x2 %0, %1, %2, %0;" : "+l"(acc) : "l"(x), "l"(w));
}
__device__ __forceinline__ ull pack2(float a, float b) {
    ull u; asm("mov.b64 %0, {%1,%2};" : "=l"(u) : "f"(a), "f"(b)); return u;
}
__device__ __forceinline__ void unpack2(ull u, float &a, float &b) {
    asm("mov.b64 {%0,%1}, %2;" : "=f"(a), "=f"(b) : "l"(u));
}

// ---------------- precompute kernels ----------------
__global__ __launch_bounds__(256) void k_prenet1(const float* __restrict__ dec,
                                                 const float* __restrict__ W1,
                                                 unsigned ka, unsigned kb)
{
    int idx = blockIdx.x * 256 + threadIdx.x;           // < 819200
    int t = idx >> 12;
    int r = idx & 4095;
    int b = r >> 8;
    int j = r & 255;
    float s = 0.f;
    if (t > 0) {
        const float* di = dec + b * (NMELS * TDEC) + (t - 1);
#pragma unroll 8
        for (int m = 0; m < NMELS; ++m)
            s += di[m * TDEC] * W1[m * PRE + j];
    }
    s = fmaxf(s, 0.f);
    s = mask_keep(ka, kb, (unsigned)idx) ? s * 2.0f : 0.f;
    g_x1[idx] = s;
}

__global__ __launch_bounds__(256) void k_prenet2(const float* __restrict__ W2,
                                                 unsigned ka, unsigned kb)
{
    int idx = blockIdx.x * 256 + threadIdx.x;
    int j = idx & 255;
    const float* x = g_x1 + (idx - j);
    float s0 = 0.f, s1 = 0.f;
#pragma unroll 8
    for (int m = 0; m < PRE; m += 2) {
        s0 += x[m]     * W2[m * PRE + j];
        s1 += x[m + 1] * W2[(m + 1) * PRE + j];
    }
    float s = fmaxf(s0 + s1, 0.f);
    s = mask_keep(ka, kb, (unsigned)idx) ? s * 2.0f : 0.f;
    g_pre[idx] = s;
}

__global__ __launch_bounds__(256) void k_pm(const float* __restrict__ memory,
                                            const float* __restrict__ Wmem)
{
    int idx = blockIdx.x * 256 + threadIdx.x;           // < 524288
    int a = idx & 127;
    int bt = idx >> 7;
    const float* me = memory + bt * EDIM;
    float s0 = 0.f, s1 = 0.f;
#pragma unroll 8
    for (int e = 0; e < EDIM; e += 2) {
        s0 += me[e]     * Wmem[e * ATT + a];
        s1 += me[e + 1] * Wmem[(e + 1) * ATT + a];
    }
    g_pm[idx] = s0 + s1;
}

// pack conv / dense weights into float2 form
__global__ __launch_bounds__(256) void k_prep(const float* __restrict__ lconv,
                                              const float* __restrict__ ldense)
{
    for (int i = threadIdx.x; i < NFILT * KSZ; i += 256) {
        int f = i / KSZ, k = i % KSZ;
        g_lconv2[i] = make_float2(lconv[f * (2 * KSZ) + k], lconv[f * (2 * KSZ) + KSZ + k]);
    }
    for (int i = threadIdx.x; i < NFILT * 64; i += 256) {
        int f = i >> 6, p = i & 63;
        g_ldense2[i] = make_float2(ldense[f * ATT + 2 * p], ldense[f * ATT + 2 * p + 1]);
    }
}

__global__ __launch_bounds__(512) void k_init()
{
    int idx = blockIdx.x * 512 + threadIdx.x;           // grid covers 524288
    if (idx == 0) { g_bar_count = 0u; g_bar_epoch = 0u; }
    if (idx < BB * HID) { g_ah[idx] = 0.f; g_ac[idx] = 0.f; g_dh[idx] = 0.f; g_dc[idx] = 0.f; }
    if (idx < BB * EDIM) g_ctx[idx] = 0.f;
    if (idx < BB * TENC) g_awpair[idx] = make_float2(0.f, 0.f);
    if (idx < BB * TENC * ATT) g_loc[idx] = 0.f;        // step-0 location features are zero
}

// ---------------- grid barrier (all 148 blocks co-resident) ----------------
__device__ __forceinline__ void gbar(unsigned &epoch)
{
    epoch += 1u;
    __syncthreads();
    if (threadIdx.x == 0) {
        __threadfence();
        if (atomicAdd(&g_bar_count, 1u) == NBLK - 1u) {
            g_bar_count = 0u;
            __threadfence();
            g_bar_epoch = epoch;
        } else {
            while (g_bar_epoch < epoch) { }
        }
    }
    __syncthreads();
}

// ---------------- GEMM phase ----------------
// 8 batches x 4 packed cols per thread. NCHUNK blocks-per-jg, 4 jg groups.
template<int L0, int IN, int CH, int NCHUNK, int MODE>
__device__ void gemm_phase(const float* __restrict__ Wih,
                           const float* __restrict__ Whh, int st, float* s_buf)
{
    int bid = blockIdx.x, tid = threadIdx.x;
    int chunk = (NCHUNK == 32) ? (bid & 31) : (bid % NCHUNK);
    int jg    = (NCHUNK == 32) ? (bid >> 5) : (bid / NCHUNK);
    int i0    = chunk * CH;
    float2* sx = (float2*)s_buf;

    for (int s = tid; s < CH * 16; s += NTHR) {
        int il = s >> 4, b = s & 15;
        int i = i0 + il;
        float v;
        if (i < L0)
            v = (MODE == 0) ? g_pre[st * (BB * PRE) + b * PRE + i]
                            : __ldcg(&g_ah[b * HID + i]);
        else if (i < IN)
            v = __ldcg(&g_ctx[b * EDIM + (i - L0)]);
        else
            v = (MODE == 0) ? __ldcg(&g_ah[b * HID + (i - IN)])
                            : __ldcg(&g_dh[b * HID + (i - IN)]);
        sx[il * 16 + b] = make_float2(v, v);
    }
    __syncthreads();

    int j0  = jg * 1024 + (tid & 255) * 4;
    int bo2 = (tid >> 8) * 4;       // ulonglong2 offset: 8 batches
    ull acc[16];
#pragma unroll
    for (int q = 0; q < 16; ++q) acc[q] = 0ull;

#pragma unroll 4
    for (int il = 0; il < CH; ++il) {
        int i = i0 + il;
        const float* wr = (i < IN) ? (Wih + (size_t)i * NG)
                                   : (Whh + (size_t)(i - IN) * NG);
        ulonglong2 w = *reinterpret_cast<const ulonglong2*>(wr + j0);
        const ulonglong2* xq = reinterpret_cast<const ulonglong2*>(sx) + il * 8 + bo2;
#pragma unroll
        for (int bp = 0; bp < 4; ++bp) {
            ulonglong2 x2 = xq[bp];
            fma2(acc[4 * bp + 0], x2.x, w.x); fma2(acc[4 * bp + 1], x2.x, w.y);
            fma2(acc[4 * bp + 2], x2.y, w.x); fma2(acc[4 * bp + 3], x2.y, w.y);
        }
    }

    float* pbase = g_partial + (size_t)chunk * (BB * NG) + j0;
#pragma unroll
    for (int bp = 0; bp < 4; ++bp) {
        int b0 = (tid >> 8) * 8 + 2 * bp;
        ulonglong2 v0; v0.x = acc[4 * bp + 0]; v0.y = acc[4 * bp + 1];
        ulonglong2 v1; v1.x = acc[4 * bp + 2]; v1.y = acc[4 * bp + 3];
        *reinterpret_cast<ulonglong2*>(pbase + (size_t)b0 * NG)       = v0;
        *reinterpret_cast<ulonglong2*>(pbase + (size_t)(b0 + 1) * NG) = v1;
    }
}

// ---------------- cell: reduce NCH partials + bias + LSTM ----------------
template<int NCH, int MODE>
__device__ void cell_phase(const float* __restrict__ bias)
{
    int gid = blockIdx.x * NTHR + threadIdx.x;
    if (gid >= BB * HID) return;
    int b = gid >> 10, u = gid & 1023;

    float z[4];
#pragma unroll
    for (int g = 0; g < 4; ++g) {
        float s = bias[g * HID + u];
        const float* pp = g_partial + (size_t)b * NG + g * HID + u;
#pragma unroll
        for (int c = 0; c < NCH; ++c) s += __ldcg(pp + (size_t)c * (BB * NG));
        z[g] = s;
    }
    float* cstate = (MODE == 0) ? g_ac : g_dc;
    float* hstate = (MODE == 0) ? g_ah : g_dh;
    float cn = fsig(z[1]) * cstate[gid] + fsig(z[0]) * ftanh(z[2]);
    float hn = fsig(z[3]) * ftanh(cn);
    cstate[gid] = cn;
    hstate[gid] = hn;
}

// ---------------- pq = ah @ Wq : warp per output ----------------
__device__ void pq_phase(const float* __restrict__ Wq, int wg, int lane)
{
    if (wg < BB * ATT) {
        int b = wg >> 7, a = wg & 127;
        const float* h = g_ah + b * HID;
        float s = 0.f;
#pragma unroll 8
        for (int k = lane; k < HID; k += 32)
            s += __ldcg(h + k) * Wq[(size_t)k * ATT + a];
#pragma unroll
        for (int off = 16; off > 0; off >>= 1) s += __shfl_down_sync(0xffffffffu, s, off);
        if (lane == 0) g_pq[wg] = s;
    }
}

// ---------------- conv + location dense -> g_loc (next step) ----------------
__device__ void convdense_phase(const int* /*unused*/, int wloc, int nwarp, int lane)
{
    for (int task = wloc; task < BB * TENC; task += nwarp) {
        int b = task >> 8, t = task & 255;

        const ull* wp = reinterpret_cast<const ull*>(g_lconv2) + lane * KSZ;
        const ull* ap = reinterpret_cast<const ull*>(g_awpair) + b * TENC;
        ull lr2 = 0ull;
#pragma unroll
        for (int k = 0; k < KSZ; ++k) {
            int tp = t + k - 15;
            if (tp >= 0 && tp < TENC) {
                ull p = __ldcg(ap + tp);
                fma2(lr2, p, wp[k]);
            }
        }
        float la, lb; unpack2(lr2, la, lb);
        float lr = la + lb;

        ull d0 = 0ull, d1 = 0ull;
        const ull* ld2 = reinterpret_cast<const ull*>(g_ldense2);
#pragma unroll
        for (int f = 0; f < NFILT; ++f) {
            float lrf = __shfl_sync(0xffffffffu, lr, f);
            ull lrf2 = pack2(lrf, lrf);
            fma2(d0, lrf2, ld2[f * 64 + lane]);
            fma2(d1, lrf2, ld2[f * 64 + lane + 32]);
        }
        ull* lout = reinterpret_cast<ull*>(g_loc + (size_t)(b * TENC + t) * ATT);
        lout[lane]      = d0;
        lout[lane + 32] = d1;
    }
}

// ---------------- energy: tanh(pq + loc + pm) . v ----------------
__device__ void energy_phase(const float* __restrict__ vw,
                             const int* __restrict__ lens, int wg, int lane)
{
    for (int task = wg; task < BB * TENC; task += GWARPS) {
        int b = task >> 8, t = task & 255;
        const float* pqb = g_pq + b * ATT;
        const float* locb = g_loc + (size_t)(b * TENC + t) * ATT;
        const float* pmb = g_pm + (size_t)(b * TENC + t) * ATT;
        float ep = 0.f;
#pragma unroll
        for (int j = 0; j < 4; ++j) {
            int a = lane + 32 * j;
            float x = __ldcg(pqb + a) + __ldcg(locb + a) + pmb[a];
            ep += ftanh(x) * vw[a];
        }
#pragma unroll
        for (int off = 16; off > 0; off >>= 1) ep += __shfl_down_sync(0xffffffffu, ep, off);
        if (lane == 0)
            g_e[b * TENC + t] = (t >= lens[b]) ? -1.0e9f : ep;
    }
}

// ---------------- softmax + awpair + alignment + context : block b ----------------
__device__ void softctx_phase(const float* __restrict__ memory, float* __restrict__ out,
                              int st, float* s_buf)
{
    int b = blockIdx.x, tid = threadIdx.x;
    float* rb  = s_buf;
    float* swv = s_buf + 256;
    float v = 0.f, p = 0.f;
    if (tid < 256) { v = __ldcg(&g_e[b * TENC + tid]); rb[tid] = v; }
    __syncthreads();
#pragma unroll
    for (int o = 128; o > 0; o >>= 1) {
        if (tid < o) rb[tid] = fmaxf(rb[tid], rb[tid + o]);
        __syncthreads();
    }
    float mx = rb[0]; __syncthreads();
    if (tid < 256) { p = __expf(v - mx); rb[tid] = p; }
    __syncthreads();
#pragma unroll
    for (int o = 128; o > 0; o >>= 1) {
        if (tid < o) rb[tid] += rb[tid + o];
        __syncthreads();
    }
    float sum = rb[0];
    if (tid < 256) {
        float w = __fdividef(p, sum);
        float2 op = g_awpair[b * TENC + tid];
        g_awpair[b * TENC + tid] = make_float2(w, op.y + w);
        out[ALIGN_OFF + (size_t)b * (TDEC * TENC) + st * TENC + tid] = w;
        swv[tid] = w;
    }
    __syncthreads();

    const float* mb = memory + (size_t)b * (TENC * EDIM) + tid;
    float c = 0.f;
#pragma unroll 8
    for (int s = 0; s < TENC; ++s)
        c += swv[s] * mb[(size_t)s * EDIM];
    g_ctx[b * EDIM + tid] = c;
}

// ---------------- projection + gate : block-per-batch, coalesced ----------------
__device__ void proj_phase(const float* __restrict__ pW, const float* __restrict__ pb,
                           const float* __restrict__ gW, const float* __restrict__ gb,
                           float* __restrict__ out, int st, int b, float* s_buf)
{
    int tid = threadIdx.x;
    float* xv  = s_buf;          // 1536
    float* red = s_buf + 1536;   // 480

    for (int i = tid; i < HID + EDIM; i += NTHR)
        xv[i] = (i < HID) ? __ldcg(&g_dh[b * HID + i]) : __ldcg(&g_ctx[b * EDIM + (i - HID)]);
    __syncthreads();

    if (tid < 480) {
        int m = tid % 80, ks = tid / 80;
        int k0 = ks * 256;
        float acc = 0.f;
#pragma unroll 8
        for (int kk = 0; kk < 256; ++kk)
            acc += xv[k0 + kk] * pW[(size_t)(k0 + kk) * NMELS + m];
        red[ks * 80 + m] = acc;
    } else {
        int lane = tid - 480;  // warp 15 exactly
        float acc = 0.f;
#pragma unroll 8
        for (int k = lane; k < HID + EDIM; k += 32)
            acc += xv[k] * gW[k];
#pragma unroll
        for (int off = 16; off > 0; off >>= 1) acc += __shfl_down_sync(0xffffffffu, acc, off);
        if (lane == 0)
            out[GATE_OFF + b * TDEC + st] = acc + gb[0];
    }
    __syncthreads();
    if (tid < 80) {
        float s = 0.f;
#pragma unroll
        for (int q = 0; q < 6; ++q) s += red[q * 80 + tid];
        out[MEL_OFF + (size_t)b * (NMELS * TDEC) + tid * TDEC + st] = s + pb[tid];
    }
    __syncthreads();
}

// ---------------- the persistent decoder kernel ----------------
__global__ __launch_bounds__(NTHR) void k_decoder(
    const float* __restrict__ memory,
    const int*   __restrict__ lens,
    const float* __restrict__ aWih, const float* __restrict__ aWhh, const float* __restrict__ ab,
    const float* __restrict__ Wq,   const float* __restrict__ vw,
    const float* __restrict__ dWih, const float* __restrict__ dWhh, const float* __restrict__ db,
    const float* __restrict__ projW, const float* __restrict__ projb,
    const float* __restrict__ gateW, const float* __restrict__ gateb,
    float* __restrict__ out)
{
    __shared__ __align__(16) float s_buf[2560];
    int bid = blockIdx.x, tid = threadIdx.x;
    int wg = bid * 16 + (tid >> 5);
    int lane = tid & 31;
    unsigned epoch = 0u;

    for (int st = 0; st < TDEC; ++st) {
        // A: GEMM1 (0..111) || proj(st-1) (132..147).  loc for this step already in g_loc.
        if (bid < 112) {
            gemm_phase<PRE, PRE + EDIM, 64, 28, 0>(aWih, aWhh, st, s_buf);
        } else if (bid >= 132 && st > 0) {
            proj_phase(projW, projb, gateW, gateb, out, st - 1, bid - 132, s_buf);
        }
        gbar(epoch);

        // B: attention LSTM cell (blocks 0..31)
        if (bid < 32) cell_phase<28, 0>(ab);
        gbar(epoch);

        // C: pq (warp per output)
        pq_phase(Wq, wg, lane);
        gbar(epoch);

        // D: energy
        energy_phase(vw, lens, wg, lane);
        gbar(epoch);

        // E: softmax + context (blocks 0..15)
        if (bid < BB) softctx_phase(memory, out, st, s_buf);
        gbar(epoch);

        // F: GEMM2 (0..127) || convdense for step st+1 (128..147)
        if (bid < 128) {
            gemm_phase<HID, HID + EDIM, 80, 32, 1>(dWih, dWhh, st, s_buf);
        } else if (st + 1 < TDEC) {
            int wloc = (bid - 128) * 16 + (tid >> 5);
            convdense_phase(lens, wloc, 20 * 16, lane);
        }
        gbar(epoch);

        // G: decoder LSTM cell (blocks 0..31)
        if (bid < 32) cell_phase<32, 1>(db);
        gbar(epoch);
    }

    // tail: projection for final step
    if (bid >= 132)
        proj_phase(projW, projb, gateW, gateb, out, TDEC - 1, bid - 132, s_buf);
}

// ---------------- launcher ----------------
extern "C" void kernel_launch(void* const* d_in, const int* in_sizes, int n_in,
                              void* d_out, int out_size)
{
    (void)in_sizes; (void)n_in; (void)out_size;
    const float* memory = (const float*)d_in[0];
    const float* dec    = (const float*)d_in[1];
    const int*   lens   = (const int*)  d_in[2];
    const float* pW1    = (const float*)d_in[3];
    const float* pW2    = (const float*)d_in[4];
    const float* aWih   = (const float*)d_in[5];
    const float* aWhh   = (const float*)d_in[6];
    const float* ab     = (const float*)d_in[7];
    const float* Wq     = (const float*)d_in[8];
    const float* Wmem   = (const float*)d_in[9];
    const float* vw     = (const float*)d_in[10];
    const float* lconv  = (const float*)d_in[11];
    const float* ldense = (const float*)d_in[12];
    const float* dWih   = (const float*)d_in[13];
    const float* dWhh   = (const float*)d_in[14];
    const float* db     = (const float*)d_in[15];
    const float* projW  = (const float*)d_in[16];
    const float* projb  = (const float*)d_in[17];
    const float* gateW  = (const float*)d_in[18];
    const float* gateb  = (const float*)d_in[19];
    float* out = (float*)d_out;

    unsigned k1a, k1b, k2a, k2b;
#if THREEFRY_PARTITIONABLE
    tf2x32(0u, 42u, 0u, 0u, k1a, k1b);
    tf2x32(0u, 42u, 0u, 1u, k2a, k2b);
#else
    {
        unsigned a0, b0, a1, b1;
        tf2x32(0u, 42u, 0u, 2u, a0, b0);
        tf2x32(0u, 42u, 1u, 3u, a1, b1);
        k1a = a0; k1b = a1; k2a = b0; k2b = b1;
    }
#endif

    k_prenet1<<<3200, 256>>>(dec, pW1, k1a, k1b);     // launch 0
    k_prenet2<<<3200, 256>>>(pW2, k2a, k2b);          // launch 1
    k_pm<<<2048, 256>>>(memory, Wmem);                // launch 2
    k_prep<<<1, 256>>>(lconv, ldense);                // launch 3
    k_init<<<1024, 512>>>();                          // launch 4

    k_decoder<<<NBLK, NTHR>>>(memory, lens,           // launch 5 (ncu -s 5 target)
                              aWih, aWhh, ab, Wq, vw,
                              dWih, dWhh, db, projW, projb, gateW, gateb, out);
}

// round 14
// speedup vs baseline: 1.2078x; 1.0901x over previous
#include <cuda_runtime.h>
#include <math.h>

// ---------------- problem constants ----------------
#define BB      16
#define TENC    256
#define TDEC    200
#define NMELS   80
#define EDIM    512
#define PRE     256
#define HID     1024     // ARNN == DRNN
#define ATT     128
#define NFILT   32
#define KSZ     31
#define NG      4096     // 4*HID

#define MEL_OFF   0
#define GATE_OFF  (BB*NMELS*TDEC)          /* 256000 */
#define ALIGN_OFF (GATE_OFF + BB*TDEC)     /* 259200 */

#define NBLK    148
#define NTHR    512
#define GWARPS  (NBLK*16)                  /* 2368 */

#define THREEFRY_PARTITIONABLE 1

typedef unsigned long long ull;

// ---------------- device scratch (no allocs allowed) ----------------
__device__ float  g_x1 [TDEC*BB*PRE];
__device__ float  g_pre[TDEC*BB*PRE];
__device__ float  g_pm [BB*TENC*ATT];
__device__ float  g_partial[32*BB*NG];         // [chunk][b][4096]
__device__ float  g_ah[BB*HID];
__device__ float  g_ac[BB*HID];
__device__ float  g_dh[BB*HID];
__device__ float  g_dc[BB*HID];
__device__ float  g_ctx[BB*EDIM];
__device__ float2 g_awpair[BB*TENC];           // (aw, awc)
__device__ float  g_pq [BB*ATT];
__device__ float  g_e  [BB*TENC];
__device__ float  g_loc[BB*TENC*ATT];          // location features
__device__ float2 g_lconv2[NFILT*KSZ];         // packed (W[f][0][k], W[f][1][k])
__device__ float2 g_ldense2[NFILT*64];         // packed col pairs

__device__ unsigned g_bar_count;
__device__ volatile unsigned g_bar_epoch;

// ---------------- threefry-2x32-20 ----------------
__host__ __device__ __forceinline__ void tf2x32(unsigned ks0, unsigned ks1,
                                                unsigned x0, unsigned x1,
                                                unsigned &o0, unsigned &o1)
{
    unsigned ks2 = ks0 ^ ks1 ^ 0x1BD11BDAu;
    x0 += ks0; x1 += ks1;
#define TFR(r) { x0 += x1; x1 = (x1 << (r)) | (x1 >> (32 - (r))); x1 ^= x0; }
    TFR(13) TFR(15) TFR(26) TFR(6)
    x0 += ks1; x1 += ks2 + 1u;
    TFR(17) TFR(29) TFR(16) TFR(24)
    x0 += ks2; x1 += ks0 + 2u;
    TFR(13) TFR(15) TFR(26) TFR(6)
    x0 += ks0; x1 += ks1 + 3u;
    TFR(17) TFR(29) TFR(16) TFR(24)
    x0 += ks1; x1 += ks2 + 4u;
    TFR(13) TFR(15) TFR(26) TFR(6)
    x0 += ks2; x1 += ks0 + 5u;
#undef TFR
    o0 = x0; o1 = x1;
}

__device__ __forceinline__ bool mask_keep(unsigned ka, unsigned kb, unsigned idx)
{
#if THREEFRY_PARTITIONABLE
    unsigned a, b;
    tf2x32(ka, kb, 0u, idx, a, b);
    return ((a ^ b) & 0x80000000u) == 0u;
#else
    const unsigned half = 411648u;
    unsigned a, b;
    if (idx < half) { tf2x32(ka, kb, idx, half + idx, a, b); return (a & 0x80000000u) == 0u; }
    else            { tf2x32(ka, kb, idx - half, idx, a, b); return (b & 0x80000000u) == 0u; }
#endif
}

// ---------------- fast transcendentals ----------------
__device__ __forceinline__ float ftanh(float x) {
    x = fminf(fmaxf(x, -15.f), 15.f);
    float e = __expf(2.f * x);
    return __fdividef(e - 1.f, e + 1.f);
}
__device__ __forceinline__ float fsig(float x) {
    x = fminf(fmaxf(x, -40.f), 40.f);
    return __fdividef(1.f, 1.f + __expf(-x));
}

__device__ __forceinline__ void fma2(ull &acc, ull x, ull w) {
    asm("fma.rn.f32x2 %0, %1, %2, %0;" : "+l"(acc) : "l"(x), "l"(w));
}
__device__ __forceinline__ ull pack2(float a, float b) {
    ull u; asm("mov.b64 %0, {%1,%2};" : "=l"(u) : "f"(a), "f"(b)); return u;
}
__device__ __forceinline__ void unpack2(ull u, float &a, float &b) {
    asm("mov.b64 {%0,%1}, %2;" : "=f"(a), "=f"(b) : "l"(u));
}

// ---------------- precompute kernels ----------------
__global__ __launch_bounds__(256) void k_prenet1(const float* __restrict__ dec,
                                                 const float* __restrict__ W1,
                                                 unsigned ka, unsigned kb)
{
    int idx = blockIdx.x * 256 + threadIdx.x;           // < 819200
    int t = idx >> 12;
    int r = idx & 4095;
    int b = r >> 8;
    int j = r & 255;
    float s = 0.f;
    if (t > 0) {
        const float* di = dec + b * (NMELS * TDEC) + (t - 1);
#pragma unroll 8
        for (int m = 0; m < NMELS; ++m)
            s += di[m * TDEC] * W1[m * PRE + j];
    }
    s = fmaxf(s, 0.f);
    s = mask_keep(ka, kb, (unsigned)idx) ? s * 2.0f : 0.f;
    g_x1[idx] = s;
}

__global__ __launch_bounds__(256) void k_prenet2(const float* __restrict__ W2,
                                                 unsigned ka, unsigned kb)
{
    int idx = blockIdx.x * 256 + threadIdx.x;
    int j = idx & 255;
    const float* x = g_x1 + (idx - j);
    float s0 = 0.f, s1 = 0.f;
#pragma unroll 8
    for (int m = 0; m < PRE; m += 2) {
        s0 += x[m]     * W2[m * PRE + j];
        s1 += x[m + 1] * W2[(m + 1) * PRE + j];
    }
    float s = fmaxf(s0 + s1, 0.f);
    s = mask_keep(ka, kb, (unsigned)idx) ? s * 2.0f : 0.f;
    g_pre[idx] = s;
}

__global__ __launch_bounds__(256) void k_pm(const float* __restrict__ memory,
                                            const float* __restrict__ Wmem)
{
    int idx = blockIdx.x * 256 + threadIdx.x;           // < 524288
    int a = idx & 127;
    int bt = idx >> 7;
    const float* me = memory + bt * EDIM;
    float s0 = 0.f, s1 = 0.f;
#pragma unroll 8
    for (int e = 0; e < EDIM; e += 2) {
        s0 += me[e]     * Wmem[e * ATT + a];
        s1 += me[e + 1] * Wmem[(e + 1) * ATT + a];
    }
    g_pm[idx] = s0 + s1;
}

__global__ __launch_bounds__(256) void k_prep(const float* __restrict__ lconv,
                                              const float* __restrict__ ldense)
{
    for (int i = threadIdx.x; i < NFILT * KSZ; i += 256) {
        int f = i / KSZ, k = i % KSZ;
        g_lconv2[i] = make_float2(lconv[f * (2 * KSZ) + k], lconv[f * (2 * KSZ) + KSZ + k]);
    }
    for (int i = threadIdx.x; i < NFILT * 64; i += 256) {
        int f = i >> 6, p = i & 63;
        g_ldense2[i] = make_float2(ldense[f * ATT + 2 * p], ldense[f * ATT + 2 * p + 1]);
    }
}

__global__ __launch_bounds__(512) void k_init()
{
    int idx = blockIdx.x * 512 + threadIdx.x;           // grid covers 524288
    if (idx == 0) { g_bar_count = 0u; g_bar_epoch = 0u; }
    if (idx < BB * HID) { g_ah[idx] = 0.f; g_ac[idx] = 0.f; g_dh[idx] = 0.f; g_dc[idx] = 0.f; }
    if (idx < BB * EDIM) g_ctx[idx] = 0.f;
    if (idx < BB * TENC) g_awpair[idx] = make_float2(0.f, 0.f);
    if (idx < BB * TENC * ATT) g_loc[idx] = 0.f;        // step-0 location features are zero
}

// ---------------- grid barrier (R9-proven epoch version) ----------------
__device__ __forceinline__ void gbar(unsigned &epoch)
{
    epoch += 1u;
    __syncthreads();
    if (threadIdx.x == 0) {
        __threadfence();
        if (atomicAdd(&g_bar_count, 1u) == NBLK - 1u) {
            g_bar_count = 0u;
            __threadfence();
            g_bar_epoch = epoch;
        } else {
            while (g_bar_epoch < epoch) { }
        }
    }
    __syncthreads();
}

// ---------------- GEMM phase ----------------
// 8 batches x 4 packed cols per thread. NCHUNK chunks x 4 jg groups.
template<int L0, int IN, int CH, int NCHUNK, int MODE>
__device__ void gemm_phase(const float* __restrict__ Wih,
                           const float* __restrict__ Whh, int st, float* s_buf)
{
    int bid = blockIdx.x, tid = threadIdx.x;
    int chunk = (NCHUNK == 32) ? (bid & 31) : (bid % NCHUNK);
    int jg    = (NCHUNK == 32) ? (bid >> 5) : (bid / NCHUNK);
    int i0    = chunk * CH;
    float2* sx = (float2*)s_buf;

    for (int s = tid; s < CH * 16; s += NTHR) {
        int il = s >> 4, b = s & 15;
        int i = i0 + il;
        float v;
        if (i < L0)
            v = (MODE == 0) ? g_pre[st * (BB * PRE) + b * PRE + i]
                            : __ldcg(&g_ah[b * HID + i]);
        else if (i < IN)
            v = __ldcg(&g_ctx[b * EDIM + (i - L0)]);
        else
            v = (MODE == 0) ? __ldcg(&g_ah[b * HID + (i - IN)])
                            : __ldcg(&g_dh[b * HID + (i - IN)]);
        sx[il * 16 + b] = make_float2(v, v);
    }
    __syncthreads();

    int j0  = jg * 1024 + (tid & 255) * 4;
    int bo2 = (tid >> 8) * 4;       // ulonglong2 offset: 8 batches
    ull acc[16];
#pragma unroll
    for (int q = 0; q < 16; ++q) acc[q] = 0ull;

#pragma unroll 4
    for (int il = 0; il < CH; ++il) {
        int i = i0 + il;
        const float* wr = (i < IN) ? (Wih + (size_t)i * NG)
                                   : (Whh + (size_t)(i - IN) * NG);
        ulonglong2 w = *reinterpret_cast<const ulonglong2*>(wr + j0);
        const ulonglong2* xq = reinterpret_cast<const ulonglong2*>(sx) + il * 8 + bo2;
#pragma unroll
        for (int bp = 0; bp < 4; ++bp) {
            ulonglong2 x2 = xq[bp];
            fma2(acc[4 * bp + 0], x2.x, w.x); fma2(acc[4 * bp + 1], x2.x, w.y);
            fma2(acc[4 * bp + 2], x2.y, w.x); fma2(acc[4 * bp + 3], x2.y, w.y);
        }
    }

    float* pbase = g_partial + (size_t)chunk * (BB * NG) + j0;
#pragma unroll
    for (int bp = 0; bp < 4; ++bp) {
        int b0 = (tid >> 8) * 8 + 2 * bp;
        ulonglong2 v0; v0.x = acc[4 * bp + 0]; v0.y = acc[4 * bp + 1];
        ulonglong2 v1; v1.x = acc[4 * bp + 2]; v1.y = acc[4 * bp + 3];
        *reinterpret_cast<ulonglong2*>(pbase + (size_t)b0 * NG)       = v0;
        *reinterpret_cast<ulonglong2*>(pbase + (size_t)(b0 + 1) * NG) = v1;
    }
}

// ---------------- cell: reduce NCH partials + bias + LSTM ----------------
template<int NCH, int MODE>
__device__ void cell_phase(const float* __restrict__ bias)
{
    int gid = blockIdx.x * NTHR + threadIdx.x;
    if (gid >= BB * HID) return;
    int b = gid >> 10, u = gid & 1023;

    float z[4];
#pragma unroll
    for (int g = 0; g < 4; ++g) {
        float s = bias[g * HID + u];
        const float* pp = g_partial + (size_t)b * NG + g * HID + u;
#pragma unroll
        for (int c = 0; c < NCH; ++c) s += __ldcg(pp + (size_t)c * (BB * NG));
        z[g] = s;
    }
    float* cstate = (MODE == 0) ? g_ac : g_dc;
    float* hstate = (MODE == 0) ? g_ah : g_dh;
    float cn = fsig(z[1]) * cstate[gid] + fsig(z[0]) * ftanh(z[2]);
    float hn = fsig(z[3]) * ftanh(cn);
    cstate[gid] = cn;
    hstate[gid] = hn;
}

// ---------------- pq = ah @ Wq : warp per output ----------------
__device__ void pq_phase(const float* __restrict__ Wq, int wg, int lane)
{
    if (wg < BB * ATT) {
        int b = wg >> 7, a = wg & 127;
        const float* h = g_ah + b * HID;
        float s = 0.f;
#pragma unroll 8
        for (int k = lane; k < HID; k += 32)
            s += __ldcg(h + k) * Wq[(size_t)k * ATT + a];
#pragma unroll
        for (int off = 16; off > 0; off >>= 1) s += __shfl_down_sync(0xffffffffu, s, off);
        if (lane == 0) g_pq[wg] = s;
    }
}

// ---------------- conv + location dense -> g_loc (next step) ----------------
__device__ void convdense_phase(int wloc, int nwarp, int lane)
{
    for (int task = wloc; task < BB * TENC; task += nwarp) {
        int b = task >> 8, t = task & 255;

        const ull* wp = reinterpret_cast<const ull*>(g_lconv2) + lane * KSZ;
        const ull* ap = reinterpret_cast<const ull*>(g_awpair) + b * TENC;
        ull lr2 = 0ull;
#pragma unroll
        for (int k = 0; k < KSZ; ++k) {
            int tp = t + k - 15;
            if (tp >= 0 && tp < TENC) {
                ull p = __ldcg(ap + tp);
                fma2(lr2, p, wp[k]);
            }
        }
        float la, lb; unpack2(lr2, la, lb);
        float lr = la + lb;

        ull d0 = 0ull, d1 = 0ull;
        const ull* ld2 = reinterpret_cast<const ull*>(g_ldense2);
#pragma unroll
        for (int f = 0; f < NFILT; ++f) {
            float lrf = __shfl_sync(0xffffffffu, lr, f);
            ull lrf2 = pack2(lrf, lrf);
            fma2(d0, lrf2, ld2[f * 64 + lane]);
            fma2(d1, lrf2, ld2[f * 64 + lane + 32]);
        }
        ull* lout = reinterpret_cast<ull*>(g_loc + (size_t)(b * TENC + t) * ATT);
        lout[lane]      = d0;
        lout[lane + 32] = d1;
    }
}

// ---------------- energy: tanh(pq + loc + pm) . v ----------------
__device__ void energy_phase(const float* __restrict__ vw,
                             const int* __restrict__ lens, int wg, int lane)
{
    for (int task = wg; task < BB * TENC; task += GWARPS) {
        int b = task >> 8, t = task & 255;
        const float* pqb = g_pq + b * ATT;
        const float* locb = g_loc + (size_t)(b * TENC + t) * ATT;
        const float* pmb = g_pm + (size_t)(b * TENC + t) * ATT;
        float ep = 0.f;
#pragma unroll
        for (int j = 0; j < 4; ++j) {
            int a = lane + 32 * j;
            float x = __ldcg(pqb + a) + __ldcg(locb + a) + pmb[a];
            ep += ftanh(x) * vw[a];
        }
#pragma unroll
        for (int off = 16; off > 0; off >>= 1) ep += __shfl_down_sync(0xffffffffu, ep, off);
        if (lane == 0)
            g_e[b * TENC + t] = (t >= lens[b]) ? -1.0e9f : ep;
    }
}

// ---------------- softmax + awpair + alignment + context : 2 blocks per batch ----------------
__device__ void softctx_phase(const float* __restrict__ memory, float* __restrict__ out,
                              int st, float* s_buf)
{
    int blk = blockIdx.x;          // 0..31
    int b = blk >> 1, half = blk & 1;
    int tid = threadIdx.x;
    float* rb   = s_buf;           // 256
    float* swv  = s_buf + 256;     // 256
    float* part = s_buf + 512;     // 512

    float v = 0.f, p = 0.f;
    if (tid < 256) { v = __ldcg(&g_e[b * TENC + tid]); rb[tid] = v; }
    __syncthreads();
#pragma unroll
    for (int o = 128; o > 0; o >>= 1) {
        if (tid < o) rb[tid] = fmaxf(rb[tid], rb[tid + o]);
        __syncthreads();
    }
    float mx = rb[0]; __syncthreads();
    if (tid < 256) { p = __expf(v - mx); rb[tid] = p; }
    __syncthreads();
#pragma unroll
    for (int o = 128; o > 0; o >>= 1) {
        if (tid < o) rb[tid] += rb[tid + o];
        __syncthreads();
    }
    float sum = rb[0];
    if (tid < 256) {
        float w = __fdividef(p, sum);
        swv[tid] = w;
        if (half == 0) {
            float2 op = g_awpair[b * TENC + tid];
            g_awpair[b * TENC + tid] = make_float2(w, op.y + w);
            out[ALIGN_OFF + (size_t)b * (TDEC * TENC) + st * TENC + tid] = w;
        }
    }
    __syncthreads();

    int col  = half * 256 + (tid & 255);
    int tsub = tid >> 8;
    const float* mb = memory + (size_t)b * (TENC * EDIM) + col;
    float c = 0.f;
#pragma unroll 8
    for (int s = tsub * 128; s < tsub * 128 + 128; ++s)
        c += swv[s] * mb[(size_t)s * EDIM];
    part[tsub * 256 + (tid & 255)] = c;
    __syncthreads();
    if (tid < 256)
        g_ctx[b * EDIM + half * 256 + tid] = part[tid] + part[256 + tid];
    __syncthreads();
}

// ---------------- projection + gate : block-per-batch, coalesced ----------------
__device__ void proj_phase(const float* __restrict__ pW, const float* __restrict__ pb,
                           const float* __restrict__ gW, const float* __restrict__ gb,
                           float* __restrict__ out, int st, int b, float* s_buf)
{
    int tid = threadIdx.x;
    float* xv  = s_buf;          // 1536
    float* red = s_buf + 1536;   // 480

    for (int i = tid; i < HID + EDIM; i += NTHR)
        xv[i] = (i < HID) ? __ldcg(&g_dh[b * HID + i]) : __ldcg(&g_ctx[b * EDIM + (i - HID)]);
    __syncthreads();

    if (tid < 480) {
        int m = tid % 80, ks = tid / 80;
        int k0 = ks * 256;
        float acc = 0.f;
#pragma unroll 8
        for (int kk = 0; kk < 256; ++kk)
            acc += xv[k0 + kk] * pW[(size_t)(k0 + kk) * NMELS + m];
        red[ks * 80 + m] = acc;
    } else {
        int lane = tid - 480;  // warp 15 exactly
        float acc = 0.f;
#pragma unroll 8
        for (int k = lane; k < HID + EDIM; k += 32)
            acc += xv[k] * gW[k];
#pragma unroll
        for (int off = 16; off > 0; off >>= 1) acc += __shfl_down_sync(0xffffffffu, acc, off);
        if (lane == 0)
            out[GATE_OFF + b * TDEC + st] = acc + gb[0];
    }
    __syncthreads();
    if (tid < 80) {
        float s = 0.f;
#pragma unroll
        for (int q = 0; q < 6; ++q) s += red[q * 80 + tid];
        out[MEL_OFF + (size_t)b * (NMELS * TDEC) + tid * TDEC + st] = s + pb[tid];
    }
    __syncthreads();
}

// ---------------- the persistent decoder kernel ----------------
__global__ __launch_bounds__(NTHR) void k_decoder(
    const float* __restrict__ memory,
    const int*   __restrict__ lens,
    const float* __restrict__ aWih, const float* __restrict__ aWhh, const float* __restrict__ ab,
    const float* __restrict__ Wq,   const float* __restrict__ vw,
    const float* __restrict__ dWih, const float* __restrict__ dWhh, const float* __restrict__ db,
    const float* __restrict__ projW, const float* __restrict__ projb,
    const float* __restrict__ gateW, const float* __restrict__ gateb,
    float* __restrict__ out)
{
    __shared__ __align__(16) float s_buf[2560];
    int bid = blockIdx.x, tid = threadIdx.x;
    int wg = bid * 16 + (tid >> 5);
    int lane = tid & 31;
    unsigned epoch = 0u;

    for (int st = 0; st < TDEC; ++st) {
        // A: gemm1(st) [0..111]  ||  proj(st-1) [132..147]
        if (bid < 112) {
            gemm_phase<PRE, PRE + EDIM, 64, 28, 0>(aWih, aWhh, st, s_buf);
        } else if (bid >= 132 && st > 0) {
            proj_phase(projW, projb, gateW, gateb, out, st - 1, bid - 132, s_buf);
        }
        gbar(epoch);

        // B: attention LSTM cell (blocks 0..31)
        if (bid < 32) cell_phase<28, 0>(ab);
        gbar(epoch);

        // C: pq (warp per output)
        pq_phase(Wq, wg, lane);
        gbar(epoch);

        // D: energy
        energy_phase(vw, lens, wg, lane);
        gbar(epoch);

        // E: softmax + context (blocks 0..31, 2 per batch)
        if (bid < 2 * BB) softctx_phase(memory, out, st, s_buf);
        gbar(epoch);

        // F: gemm2(st) [0..127]  ||  convdense(st+1) [128..147]
        if (bid < 128) {
            gemm_phase<HID, HID + EDIM, 80, 32, 1>(dWih, dWhh, st, s_buf);
        } else if (st + 1 < TDEC) {
            int wloc = (bid - 128) * 16 + (tid >> 5);
            convdense_phase(wloc, 20 * 16, lane);
        }
        gbar(epoch);

        // G: decoder LSTM cell (blocks 0..31)
        if (bid < 32) cell_phase<32, 1>(db);
        gbar(epoch);
    }

    // tail: projection for final step
    if (bid >= 132)
        proj_phase(projW, projb, gateW, gateb, out, TDEC - 1, bid - 132, s_buf);
}

// ---------------- launcher ----------------
extern "C" void kernel_launch(void* const* d_in, const int* in_sizes, int n_in,
                              void* d_out, int out_size)
{
    (void)in_sizes; (void)n_in; (void)out_size;
    const float* memory = (const float*)d_in[0];
    const float* dec    = (const float*)d_in[1];
    const int*   lens   = (const int*)  d_in[2];
    const float* pW1    = (const float*)d_in[3];
    const float* pW2    = (const float*)d_in[4];
    const float* aWih   = (const float*)d_in[5];
    const float* aWhh   = (const float*)d_in[6];
    const float* ab     = (const float*)d_in[7];
    const float* Wq     = (const float*)d_in[8];
    const float* Wmem   = (const float*)d_in[9];
    const float* vw     = (const float*)d_in[10];
    const float* lconv  = (const float*)d_in[11];
    const float* ldense = (const float*)d_in[12];
    const float* dWih   = (const float*)d_in[13];
    const float* dWhh   = (const float*)d_in[14];
    const float* db     = (const float*)d_in[15];
    const float* projW  = (const float*)d_in[16];
    const float* projb  = (const float*)d_in[17];
    const float* gateW  = (const float*)d_in[18];
    const float* gateb  = (const float*)d_in[19];
    float* out = (float*)d_out;

    unsigned k1a, k1b, k2a, k2b;
#if THREEFRY_PARTITIONABLE
    tf2x32(0u, 42u, 0u, 0u, k1a, k1b);
    tf2x32(0u, 42u, 0u, 1u, k2a, k2b);
#else
    {
        unsigned a0, b0, a1, b1;
        tf2x32(0u, 42u, 0u, 2u, a0, b0);
        tf2x32(0u, 42u, 1u, 3u, a1, b1);
        k1a = a0; k1b = a1; k2a = b0; k2b = b1;
    }
#endif

    k_prenet1<<<3200, 256>>>(dec, pW1, k1a, k1b);
    k_prenet2<<<3200, 256>>>(pW2, k2a, k2b);
    k_pm<<<2048, 256>>>(memory, Wmem);
    k_prep<<<1, 256>>>(lconv, ldense);
    k_init<<<1024, 512>>>();

    k_decoder<<<NBLK, NTHR>>>(memory, lens,
                              aWih, aWhh, ab, Wq, vw,
                              dWih, dWhh, db, projW, projb, gateW, gateb, out);
}